// round 1
// baseline (speedup 1.0000x reference)
#include <cuda_runtime.h>
#include <math.h>

// Problem constants (fixed by the reference generator)
#define NN   20000
#define DD   512
#define HH   8
#define DHH  64
#define FF   2048
#define LLAY 2
#define EE   320000

// ---------------------------------------------------------------------------
// Scratch (device globals: alloc-free rule)
// ---------------------------------------------------------------------------
__device__ float g_q  [NN * DD];
__device__ float g_k  [NN * DD];
__device__ float g_v  [NN * DD];
__device__ float g_agg[NN * DD];
__device__ float g_t  [NN * DD];   // attn-out / ff2-out
__device__ float g_x  [NN * DD];   // running activations
__device__ float g_ff [NN * FF];
__device__ float g_p  [EE * HH];   // scores, then exp(scores - m)
__device__ float g_m  [NN * HH];   // per (node, head) max
__device__ float g_s  [NN * HH];   // per (node, head) sum
__device__ float g_sums[2 * DD];   // batchnorm column sums (sum, sumsq)
__device__ float g_mu [DD];
__device__ float g_rs [DD];

// ---------------------------------------------------------------------------
// Utility kernels
// ---------------------------------------------------------------------------
__global__ void fill_k(float* __restrict__ p, float v, int n) {
    int i = blockIdx.x * blockDim.x + threadIdx.x;
    if (i < n) p[i] = v;
}

// ---------------------------------------------------------------------------
// Tiled fp32 GEMM: C[M, Nout] = act( (A[M,K] @ W[Nout,K]^T + bias) * scale )
// Both A and W are row-major with contiguous K ("NT" layout).
// Tile 64x64, BK=16, 256 threads, 4x4 microtile per thread.
// ---------------------------------------------------------------------------
template <bool RELU>
__global__ void __launch_bounds__(256)
gemm_nt(const float* __restrict__ A, const float* __restrict__ W,
        const float* __restrict__ bias, float* __restrict__ C,
        int M, int K, int Nout, float scale)
{
    __shared__ float As[16][64];   // [k][row]
    __shared__ float Ws[16][64];   // [k][col]

    const int t  = threadIdx.x;
    const int tx = t & 15;         // 0..15  -> output col group
    const int ty = t >> 4;         // 0..15  -> output row group
    const int rowBase = blockIdx.y * 64;
    const int colBase = blockIdx.x * 64;

    // loader mapping: 256 threads load 64 rows x 16 k as float4
    const int lr = t >> 2;          // 0..63
    const int lc = (t & 3) << 2;    // 0,4,8,12

    float acc[4][4];
#pragma unroll
    for (int i = 0; i < 4; i++)
#pragma unroll
        for (int j = 0; j < 4; j++) acc[i][j] = 0.f;

    const int ar = rowBase + lr;
    const int wr = colBase + lr;    // always < Nout (Nout % 64 == 0)

    for (int k0 = 0; k0 < K; k0 += 16) {
        float4 av = make_float4(0.f, 0.f, 0.f, 0.f);
        if (ar < M) av = *(const float4*)(A + (size_t)ar * K + k0 + lc);
        float4 wv = *(const float4*)(W + (size_t)wr * K + k0 + lc);

        __syncthreads();
        As[lc + 0][lr] = av.x; As[lc + 1][lr] = av.y;
        As[lc + 2][lr] = av.z; As[lc + 3][lr] = av.w;
        Ws[lc + 0][lr] = wv.x; Ws[lc + 1][lr] = wv.y;
        Ws[lc + 2][lr] = wv.z; Ws[lc + 3][lr] = wv.w;
        __syncthreads();

#pragma unroll
        for (int kk = 0; kk < 16; kk++) {
            float4 a4 = *(const float4*)&As[kk][ty << 2];
            float4 b4 = *(const float4*)&Ws[kk][tx << 2];
            float a[4] = {a4.x, a4.y, a4.z, a4.w};
            float b[4] = {b4.x, b4.y, b4.z, b4.w};
#pragma unroll
            for (int i = 0; i < 4; i++)
#pragma unroll
                for (int j = 0; j < 4; j++)
                    acc[i][j] = fmaf(a[i], b[j], acc[i][j]);
        }
    }

    const int c0 = colBase + (tx << 2);
    float4 bia = make_float4(0.f, 0.f, 0.f, 0.f);
    if (bias) bia = *(const float4*)(bias + c0);

#pragma unroll
    for (int i = 0; i < 4; i++) {
        int r = rowBase + (ty << 2) + i;
        if (r >= M) continue;
        float4 o;
        o.x = (acc[i][0] + bia.x) * scale;
        o.y = (acc[i][1] + bia.y) * scale;
        o.z = (acc[i][2] + bia.z) * scale;
        o.w = (acc[i][3] + bia.w) * scale;
        if (RELU) {
            o.x = fmaxf(o.x, 0.f); o.y = fmaxf(o.y, 0.f);
            o.z = fmaxf(o.z, 0.f); o.w = fmaxf(o.w, 0.f);
        }
        *(float4*)(C + (size_t)r * Nout + c0) = o;
    }
}

// ---------------------------------------------------------------------------
// Edge phase
// ---------------------------------------------------------------------------
__device__ __forceinline__ void atomicMaxFloat(float* addr, float val) {
    int* ai = (int*)addr;
    int old = *ai;
    while (__int_as_float(old) < val) {
        int assumed = old;
        old = atomicCAS(ai, assumed, __float_as_int(val));
        if (old == assumed) break;
    }
}

// one warp per edge; lane covers 16 contiguous d's (lanes 4h..4h+3 = head h)
__global__ void edge_scores(const float* __restrict__ q, const float* __restrict__ k,
                            const int* __restrict__ srcI, const int* __restrict__ tgtI,
                            float* __restrict__ scores, float* __restrict__ m, int E)
{
    int w = (blockIdx.x * blockDim.x + threadIdx.x) >> 5;
    int lane = threadIdx.x & 31;
    if (w >= E) return;
    int tn = tgtI[w], sn = srcI[w];
    const float4* qr = (const float4*)(q + (size_t)tn * DD);
    const float4* kr = (const float4*)(k + (size_t)sn * DD);
    float acc = 0.f;
#pragma unroll
    for (int i = 0; i < 4; i++) {
        float4 a = qr[lane * 4 + i];
        float4 b = kr[lane * 4 + i];
        acc += a.x * b.x + a.y * b.y + a.z * b.z + a.w * b.w;
    }
    acc += __shfl_xor_sync(0xffffffffu, acc, 1);
    acc += __shfl_xor_sync(0xffffffffu, acc, 2);
    if ((lane & 3) == 0) {
        int h = lane >> 2;
        scores[(size_t)w * HH + h] = acc;
        atomicMaxFloat(&m[tn * HH + h], acc);
    }
}

__global__ void edge_exp(const int* __restrict__ tgtI,
                         float* __restrict__ scores,
                         const float* __restrict__ m,
                         float* __restrict__ s, int E)
{
    int idx = blockIdx.x * blockDim.x + threadIdx.x;
    if (idx >= E * HH) return;
    int e = idx >> 3, h = idx & 7;
    int tn = tgtI[e];
    float p = expf(scores[idx] - m[tn * HH + h]);
    scores[idx] = p;
    atomicAdd(&s[tn * HH + h], p);
}

// one warp per edge: agg[tgt] += (p/s) * v[src]
__global__ void edge_agg(const float* __restrict__ v,
                         const int* __restrict__ srcI, const int* __restrict__ tgtI,
                         const float* __restrict__ p, const float* __restrict__ s,
                         float* __restrict__ agg, int E)
{
    int w = (blockIdx.x * blockDim.x + threadIdx.x) >> 5;
    int lane = threadIdx.x & 31;
    if (w >= E) return;
    int tn = tgtI[w], sn = srcI[w];
    int h = lane >> 2;
    float pe  = p[(size_t)w * HH + h];
    float den = s[tn * HH + h];
    float wt  = pe / (den + 1e-16f);
    const float4* vr = (const float4*)(v + (size_t)sn * DD);
    float* ag = agg + (size_t)tn * DD + lane * 16;
#pragma unroll
    for (int i = 0; i < 4; i++) {
        float4 vv = vr[lane * 4 + i];
        atomicAdd(&ag[i * 4 + 0], wt * vv.x);
        atomicAdd(&ag[i * 4 + 1], wt * vv.y);
        atomicAdd(&ag[i * 4 + 2], wt * vv.z);
        atomicAdd(&ag[i * 4 + 3], wt * vv.w);
    }
}

// ---------------------------------------------------------------------------
// BatchNorm over node dimension on z = a + b (residual fused)
// ---------------------------------------------------------------------------
__global__ void bn_stats(const float* __restrict__ a, const float* __restrict__ b,
                         float* __restrict__ sums, int n)
{
    int j = threadIdx.x;   // 512 threads = one per feature
    float sum = 0.f, sq = 0.f;
    for (int i = blockIdx.x; i < n; i += gridDim.x) {
        float z = a[(size_t)i * DD + j] + b[(size_t)i * DD + j];
        sum += z; sq += z * z;
    }
    atomicAdd(&sums[j], sum);
    atomicAdd(&sums[DD + j], sq);
}

__global__ void bn_finalize(const float* __restrict__ sums,
                            float* __restrict__ mu, float* __restrict__ rs, float invn)
{
    int j = threadIdx.x;
    float m = sums[j] * invn;
    float var = sums[DD + j] * invn - m * m;
    mu[j] = m;
    rs[j] = rsqrtf(var + 1e-5f);
}

__global__ void bn_apply(const float* __restrict__ a, const float* __restrict__ b,
                         const float* __restrict__ mu, const float* __restrict__ rs,
                         const float* __restrict__ g, const float* __restrict__ beta,
                         float* __restrict__ out, int n)
{
    int idx = blockIdx.x * blockDim.x + threadIdx.x;
    if (idx >= n * DD) return;
    int j = idx & (DD - 1);
    float z = a[idx] + b[idx];
    out[idx] = (z - mu[j]) * rs[j] * g[j] + beta[j];
}

// ---------------------------------------------------------------------------
// Final per-row LayerNorm  (128 threads/row, 4 floats each)
// ---------------------------------------------------------------------------
__global__ void layernorm_k(const float* __restrict__ x, const float* __restrict__ g,
                            const float* __restrict__ b, float* __restrict__ out)
{
    int row = blockIdx.x;
    int t = threadIdx.x;
    const float4* xr = (const float4*)(x + (size_t)row * DD);
    float4 v = xr[t];
    float sum = v.x + v.y + v.z + v.w;
    float sq  = v.x * v.x + v.y * v.y + v.z * v.z + v.w * v.w;

#pragma unroll
    for (int o = 16; o > 0; o >>= 1) {
        sum += __shfl_xor_sync(0xffffffffu, sum, o);
        sq  += __shfl_xor_sync(0xffffffffu, sq, o);
    }
    __shared__ float sa[4], sb[4];
    int w = t >> 5, l = t & 31;
    if (l == 0) { sa[w] = sum; sb[w] = sq; }
    __syncthreads();
    sum = sa[0] + sa[1] + sa[2] + sa[3];
    sq  = sb[0] + sb[1] + sb[2] + sb[3];

    float mu = sum * (1.f / DD);
    float var = sq * (1.f / DD) - mu * mu;
    float rs = rsqrtf(var + 1e-5f);

    const float4* g4 = (const float4*)g;
    const float4* b4 = (const float4*)b;
    float4 gg = g4[t], bb = b4[t];
    float4 o;
    o.x = (v.x - mu) * rs * gg.x + bb.x;
    o.y = (v.y - mu) * rs * gg.y + bb.y;
    o.z = (v.z - mu) * rs * gg.z + bb.z;
    o.w = (v.w - mu) * rs * gg.w + bb.w;
    *(float4*)(out + (size_t)row * DD + t * 4) = o;
}

// ---------------------------------------------------------------------------
// Orchestration
// ---------------------------------------------------------------------------
extern "C" void kernel_launch(void* const* d_in, const int* in_sizes, int n_in,
                              void* d_out, int out_size)
{
    const float* src = (const float*)d_in[0];
    const int*   ei  = (const int*)  d_in[1];
    const float* Wq  = (const float*)d_in[2];
    const float* bq  = (const float*)d_in[3];
    const float* Wk  = (const float*)d_in[4];
    const float* Wv  = (const float*)d_in[5];
    const float* Wo  = (const float*)d_in[6];
    const float* bo  = (const float*)d_in[7];
    const float* W1  = (const float*)d_in[8];
    const float* b1  = (const float*)d_in[9];
    const float* W2  = (const float*)d_in[10];
    const float* b2  = (const float*)d_in[11];
    const float* g1  = (const float*)d_in[12];
    const float* be1 = (const float*)d_in[13];
    const float* g2  = (const float*)d_in[14];
    const float* be2 = (const float*)d_in[15];
    const float* lng = (const float*)d_in[16];
    const float* lnb = (const float*)d_in[17];
    float* outp = (float*)d_out;

    const int n = in_sizes[0] / DD;
    const int E = in_sizes[1] / 2;
    const int* srcI = ei;
    const int* tgtI = ei + E;

    float *q, *k, *v, *agg, *tb, *x, *ff, *p, *m, *s, *sums, *mu, *rs;
    cudaGetSymbolAddress((void**)&q,   g_q);
    cudaGetSymbolAddress((void**)&k,   g_k);
    cudaGetSymbolAddress((void**)&v,   g_v);
    cudaGetSymbolAddress((void**)&agg, g_agg);
    cudaGetSymbolAddress((void**)&tb,  g_t);
    cudaGetSymbolAddress((void**)&x,   g_x);
    cudaGetSymbolAddress((void**)&ff,  g_ff);
    cudaGetSymbolAddress((void**)&p,   g_p);
    cudaGetSymbolAddress((void**)&m,   g_m);
    cudaGetSymbolAddress((void**)&s,   g_s);
    cudaGetSymbolAddress((void**)&sums, g_sums);
    cudaGetSymbolAddress((void**)&mu,  g_mu);
    cudaGetSymbolAddress((void**)&rs,  g_rs);

    const float scaling = 0.125f;   // DH^-0.5, DH=64
    const dim3 gD(DD / 64, (n + 63) / 64);   // GEMM [n, D]
    const dim3 gF(FF / 64, (n + 63) / 64);   // GEMM [n, F]
    const int edgeWarpBlocks = (E + 7) / 8;        // 8 warps/block
    const int edgeEHBlocks   = (E * HH + 255) / 256;
    const int nDblocks       = (n * DD + 255) / 256;

    const float* xin = src;

    for (int l = 0; l < LLAY; l++) {
        const float* Wql = Wq + (size_t)l * DD * DD;
        const float* Wkl = Wk + (size_t)l * DD * DD;
        const float* Wvl = Wv + (size_t)l * DD * DD;
        const float* Wol = Wo + (size_t)l * DD * DD;
        const float* W1l = W1 + (size_t)l * FF * DD;
        const float* W2l = W2 + (size_t)l * DD * FF;

        // q, k, v projections
        gemm_nt<false><<<gD, 256>>>(xin, Wql, bq + l * DD, q, n, DD, DD, scaling);
        gemm_nt<false><<<gD, 256>>>(xin, Wkl, nullptr,     k, n, DD, DD, 1.f);
        gemm_nt<false><<<gD, 256>>>(xin, Wvl, nullptr,     v, n, DD, DD, 1.f);

        // edge softmax + aggregation
        fill_k<<<(n * HH + 255) / 256, 256>>>(m, -INFINITY, n * HH);
        fill_k<<<(n * HH + 255) / 256, 256>>>(s, 0.f, n * HH);
        fill_k<<<nDblocks, 256>>>(agg, 0.f, n * DD);
        edge_scores<<<edgeWarpBlocks, 256>>>(q, k, srcI, tgtI, p, m, E);
        edge_exp<<<edgeEHBlocks, 256>>>(tgtI, p, m, s, E);
        edge_agg<<<edgeWarpBlocks, 256>>>(v, srcI, tgtI, p, s, agg, E);

        // output projection
        gemm_nt<false><<<gD, 256>>>(agg, Wol, bo + l * DD, tb, n, DD, DD, 1.f);

        // batchnorm 1 (residual xin + tb)
        fill_k<<<(2 * DD + 255) / 256, 256>>>(sums, 0.f, 2 * DD);
        bn_stats<<<256, DD>>>(xin, tb, sums, n);
        bn_finalize<<<1, DD>>>(sums, mu, rs, 1.f / (float)n);
        bn_apply<<<nDblocks, 256>>>(xin, tb, mu, rs, g1 + l * DD, be1 + l * DD, x, n);

        // feedforward
        gemm_nt<true ><<<gF, 256>>>(x, W1l, b1 + l * FF, ff, n, DD, FF, 1.f);
        gemm_nt<false><<<gD, 256>>>(ff, W2l, b2 + l * DD, tb, n, FF, DD, 1.f);

        // batchnorm 2 (residual x + tb), in-place on x
        fill_k<<<(2 * DD + 255) / 256, 256>>>(sums, 0.f, 2 * DD);
        bn_stats<<<256, DD>>>(x, tb, sums, n);
        bn_finalize<<<1, DD>>>(sums, mu, rs, 1.f / (float)n);
        bn_apply<<<nDblocks, 256>>>(x, tb, mu, rs, g2 + l * DD, be2 + l * DD, x, n);

        xin = x;
    }

    // final layernorm -> output
    layernorm_k<<<n, 128>>>(x, lng, lnb, outp);
}

// round 2
// speedup vs baseline: 2.2314x; 2.2314x over previous
#include <cuda_runtime.h>
#include <math.h>
#include <stdint.h>

// Problem constants (fixed by the reference generator)
#define NN   20000
#define DD   512
#define HH   8
#define DHH  64
#define FF   2048
#define LLAY 2
#define EE   320000

// ---------------------------------------------------------------------------
// Scratch (device globals: alloc-free rule)
// ---------------------------------------------------------------------------
__device__ float g_q  [NN * DD];
__device__ float g_k  [NN * DD];
__device__ float g_v  [NN * DD];
__device__ float g_agg[NN * DD];
__device__ float g_t  [NN * DD];   // attn-out / ff2-out
__device__ float g_x  [NN * DD];   // running activations
__device__ float g_ff [NN * FF];
__device__ float g_p  [EE * HH];   // scores, then exp(scores - m)
__device__ float g_m  [NN * HH];   // per (node, head) max
__device__ float g_s  [NN * HH];   // per (node, head) sum
__device__ float g_sums[2 * DD];   // batchnorm column sums (sum, sumsq)
__device__ float g_mu [DD];
__device__ float g_rs [DD];

// ---------------------------------------------------------------------------
// Utility kernels
// ---------------------------------------------------------------------------
__global__ void fill_k(float* __restrict__ p, float v, int n) {
    int i = blockIdx.x * blockDim.x + threadIdx.x;
    if (i < n) p[i] = v;
}

__global__ void init_ms(float* __restrict__ m, float* __restrict__ s, int n) {
    int i = blockIdx.x * blockDim.x + threadIdx.x;
    if (i < n) { m[i] = -INFINITY; s[i] = 0.f; }
}

// ---------------------------------------------------------------------------
// TF32 tensor-core GEMM: C[M,Nout] = act((A[M,K] @ W[Nout,K]^T + bias)*scale)
// Block tile 128x128, BK=32, 256 threads (8 warps, 2x4), warp tile 64x32.
// mma.sync.aligned.m16n8k8.row.col.f32.tf32.tf32.f32
// ---------------------------------------------------------------------------
__device__ __forceinline__ uint32_t f2tf(float x) {
    uint32_t r;
    asm("cvt.rna.tf32.f32 %0, %1;" : "=r"(r) : "f"(x));
    return r;
}

template <bool RELU>
__global__ void __launch_bounds__(256, 1)
gemm_tf32(const float* __restrict__ A, const float* __restrict__ W,
          const float* __restrict__ bias, float* __restrict__ C,
          int M, int K, int Nout, float scale)
{
    __shared__ float As[128][36];   // [m][k] padded: frag loads conflict-free
    __shared__ float Bs[128][36];   // [n][k]

    const int tid  = threadIdx.x;
    const int lane = tid & 31;
    const int warp = tid >> 5;
    const int wm   = warp >> 2;     // 0..1
    const int wn   = warp & 3;      // 0..3
    const int g    = lane >> 2;     // 0..7
    const int c    = lane & 3;      // 0..3
    const int rowBase = blockIdx.y * 128;
    const int colBase = blockIdx.x * 128;

    float acc[4][4][4];
#pragma unroll
    for (int mt = 0; mt < 4; mt++)
#pragma unroll
        for (int nt = 0; nt < 4; nt++)
#pragma unroll
            for (int i = 0; i < 4; i++) acc[mt][nt][i] = 0.f;

    float4 aR[4], bR[4];

    auto loadTiles = [&](int k0) {
#pragma unroll
        for (int i = 0; i < 4; i++) {
            int li = tid + i * 256;       // 0..1023 float4 slots
            int r  = li >> 3;             // 0..127
            int q  = li & 7;              // 0..7 (quad of 4 k's)
            int ar = rowBase + r;
            aR[i] = (ar < M) ? *(const float4*)(A + (size_t)ar * K + k0 + q * 4)
                             : make_float4(0.f, 0.f, 0.f, 0.f);
            bR[i] = *(const float4*)(W + (size_t)(colBase + r) * K + k0 + q * 4);
        }
    };

    auto storeTiles = [&]() {
#pragma unroll
        for (int i = 0; i < 4; i++) {
            int li = tid + i * 256;
            int r  = li >> 3;
            int q  = li & 7;
            float4 av, bv;
            av.x = __uint_as_float(f2tf(aR[i].x));
            av.y = __uint_as_float(f2tf(aR[i].y));
            av.z = __uint_as_float(f2tf(aR[i].z));
            av.w = __uint_as_float(f2tf(aR[i].w));
            bv.x = __uint_as_float(f2tf(bR[i].x));
            bv.y = __uint_as_float(f2tf(bR[i].y));
            bv.z = __uint_as_float(f2tf(bR[i].z));
            bv.w = __uint_as_float(f2tf(bR[i].w));
            *(float4*)&As[r][q * 4] = av;
            *(float4*)&Bs[r][q * 4] = bv;
        }
    };

    loadTiles(0);
    const int nIter = K >> 5;

    for (int kt = 0; kt < nIter; kt++) {
        __syncthreads();
        storeTiles();
        __syncthreads();
        if (kt + 1 < nIter) loadTiles((kt + 1) << 5);

#pragma unroll
        for (int ks = 0; ks < 4; ks++) {
            uint32_t af[4][4];
            uint32_t bf[4][2];
#pragma unroll
            for (int mt = 0; mt < 4; mt++) {
                int r0 = wm * 64 + mt * 16 + g;
                af[mt][0] = __float_as_uint(As[r0    ][ks * 8 + c    ]);
                af[mt][1] = __float_as_uint(As[r0 + 8][ks * 8 + c    ]);
                af[mt][2] = __float_as_uint(As[r0    ][ks * 8 + c + 4]);
                af[mt][3] = __float_as_uint(As[r0 + 8][ks * 8 + c + 4]);
            }
#pragma unroll
            for (int nt = 0; nt < 4; nt++) {
                int n0 = wn * 32 + nt * 8 + g;
                bf[nt][0] = __float_as_uint(Bs[n0][ks * 8 + c    ]);
                bf[nt][1] = __float_as_uint(Bs[n0][ks * 8 + c + 4]);
            }
#pragma unroll
            for (int mt = 0; mt < 4; mt++)
#pragma unroll
                for (int nt = 0; nt < 4; nt++)
                    asm volatile(
                        "mma.sync.aligned.m16n8k8.row.col.f32.tf32.tf32.f32 "
                        "{%0,%1,%2,%3}, {%4,%5,%6,%7}, {%8,%9}, {%0,%1,%2,%3};"
                        : "+f"(acc[mt][nt][0]), "+f"(acc[mt][nt][1]),
                          "+f"(acc[mt][nt][2]), "+f"(acc[mt][nt][3])
                        : "r"(af[mt][0]), "r"(af[mt][1]),
                          "r"(af[mt][2]), "r"(af[mt][3]),
                          "r"(bf[nt][0]), "r"(bf[nt][1]));
        }
    }

    // Epilogue: bias, scale, relu, guarded float2 stores
#pragma unroll
    for (int mt = 0; mt < 4; mt++) {
        int r0 = rowBase + wm * 64 + mt * 16 + g;
        int r1 = r0 + 8;
#pragma unroll
        for (int nt = 0; nt < 4; nt++) {
            int col = colBase + wn * 32 + nt * 8 + c * 2;
            float bx = 0.f, by = 0.f;
            if (bias) { float2 bb = *(const float2*)(bias + col); bx = bb.x; by = bb.y; }
            float v0 = (acc[mt][nt][0] + bx) * scale;
            float v1 = (acc[mt][nt][1] + by) * scale;
            float v2 = (acc[mt][nt][2] + bx) * scale;
            float v3 = (acc[mt][nt][3] + by) * scale;
            if (RELU) {
                v0 = fmaxf(v0, 0.f); v1 = fmaxf(v1, 0.f);
                v2 = fmaxf(v2, 0.f); v3 = fmaxf(v3, 0.f);
            }
            if (r0 < M) *(float2*)(C + (size_t)r0 * Nout + col) = make_float2(v0, v1);
            if (r1 < M) *(float2*)(C + (size_t)r1 * Nout + col) = make_float2(v2, v3);
        }
    }
}

// ---------------------------------------------------------------------------
// Edge phase
// ---------------------------------------------------------------------------
__device__ __forceinline__ void atomicMaxFloat(float* addr, float val) {
    int* ai = (int*)addr;
    int old = *ai;
    while (__int_as_float(old) < val) {
        int assumed = old;
        old = atomicCAS(ai, assumed, __float_as_int(val));
        if (old == assumed) break;
    }
}

__global__ void edge_scores(const float* __restrict__ q, const float* __restrict__ k,
                            const int* __restrict__ srcI, const int* __restrict__ tgtI,
                            float* __restrict__ scores, float* __restrict__ m, int E)
{
    int w = (blockIdx.x * blockDim.x + threadIdx.x) >> 5;
    int lane = threadIdx.x & 31;
    if (w >= E) return;
    int tn = tgtI[w], sn = srcI[w];
    const float4* qr = (const float4*)(q + (size_t)tn * DD);
    const float4* kr = (const float4*)(k + (size_t)sn * DD);
    float acc = 0.f;
#pragma unroll
    for (int i = 0; i < 4; i++) {
        float4 a = qr[lane * 4 + i];
        float4 b = kr[lane * 4 + i];
        acc += a.x * b.x + a.y * b.y + a.z * b.z + a.w * b.w;
    }
    acc += __shfl_xor_sync(0xffffffffu, acc, 1);
    acc += __shfl_xor_sync(0xffffffffu, acc, 2);
    if ((lane & 3) == 0) {
        int h = lane >> 2;
        scores[(size_t)w * HH + h] = acc;
        atomicMaxFloat(&m[tn * HH + h], acc);
    }
}

__global__ void edge_exp(const int* __restrict__ tgtI,
                         float* __restrict__ scores,
                         const float* __restrict__ m,
                         float* __restrict__ s, int E)
{
    int idx = blockIdx.x * blockDim.x + threadIdx.x;
    if (idx >= E * HH) return;
    int e = idx >> 3, h = idx & 7;
    int tn = tgtI[e];
    float p = expf(scores[idx] - m[tn * HH + h]);
    scores[idx] = p;
    atomicAdd(&s[tn * HH + h], p);
}

__global__ void edge_agg(const float* __restrict__ v,
                         const int* __restrict__ srcI, const int* __restrict__ tgtI,
                         const float* __restrict__ p, const float* __restrict__ s,
                         float* __restrict__ agg, int E)
{
    int w = (blockIdx.x * blockDim.x + threadIdx.x) >> 5;
    int lane = threadIdx.x & 31;
    if (w >= E) return;
    int tn = tgtI[w], sn = srcI[w];
    int h = lane >> 2;
    float pe  = p[(size_t)w * HH + h];
    float den = s[tn * HH + h];
    float wt  = pe / (den + 1e-16f);
    const float4* vr = (const float4*)(v + (size_t)sn * DD);
    float* ag = agg + (size_t)tn * DD + lane * 16;
#pragma unroll
    for (int i = 0; i < 4; i++) {
        float4 vv = vr[lane * 4 + i];
        atomicAdd(&ag[i * 4 + 0], wt * vv.x);
        atomicAdd(&ag[i * 4 + 1], wt * vv.y);
        atomicAdd(&ag[i * 4 + 2], wt * vv.z);
        atomicAdd(&ag[i * 4 + 3], wt * vv.w);
    }
}

// ---------------------------------------------------------------------------
// BatchNorm over node dimension on z = a + b (residual fused)
// ---------------------------------------------------------------------------
__global__ void bn_stats(const float* __restrict__ a, const float* __restrict__ b,
                         float* __restrict__ sums, int n)
{
    int j = threadIdx.x;   // 512 threads = one per feature
    float sum = 0.f, sq = 0.f;
    for (int i = blockIdx.x; i < n; i += gridDim.x) {
        float z = a[(size_t)i * DD + j] + b[(size_t)i * DD + j];
        sum += z; sq += z * z;
    }
    atomicAdd(&sums[j], sum);
    atomicAdd(&sums[DD + j], sq);
}

__global__ void bn_finalize(const float* __restrict__ sums,
                            float* __restrict__ mu, float* __restrict__ rs, float invn)
{
    int j = threadIdx.x;
    float m = sums[j] * invn;
    float var = sums[DD + j] * invn - m * m;
    mu[j] = m;
    rs[j] = rsqrtf(var + 1e-5f);
}

__global__ void bn_apply(const float* __restrict__ a, const float* __restrict__ b,
                         const float* __restrict__ mu, const float* __restrict__ rs,
                         const float* __restrict__ g, const float* __restrict__ beta,
                         float* __restrict__ out, int n)
{
    int idx = blockIdx.x * blockDim.x + threadIdx.x;
    if (idx >= n * DD) return;
    int j = idx & (DD - 1);
    float z = a[idx] + b[idx];
    out[idx] = (z - mu[j]) * rs[j] * g[j] + beta[j];
}

// ---------------------------------------------------------------------------
// Final per-row LayerNorm  (128 threads/row, 4 floats each)
// ---------------------------------------------------------------------------
__global__ void layernorm_k(const float* __restrict__ x, const float* __restrict__ g,
                            const float* __restrict__ b, float* __restrict__ out)
{
    int row = blockIdx.x;
    int t = threadIdx.x;
    const float4* xr = (const float4*)(x + (size_t)row * DD);
    float4 v = xr[t];
    float sum = v.x + v.y + v.z + v.w;
    float sq  = v.x * v.x + v.y * v.y + v.z * v.z + v.w * v.w;

#pragma unroll
    for (int o = 16; o > 0; o >>= 1) {
        sum += __shfl_xor_sync(0xffffffffu, sum, o);
        sq  += __shfl_xor_sync(0xffffffffu, sq, o);
    }
    __shared__ float sa[4], sb[4];
    int w = t >> 5, l = t & 31;
    if (l == 0) { sa[w] = sum; sb[w] = sq; }
    __syncthreads();
    sum = sa[0] + sa[1] + sa[2] + sa[3];
    sq  = sb[0] + sb[1] + sb[2] + sb[3];

    float mu = sum * (1.f / DD);
    float var = sq * (1.f / DD) - mu * mu;
    float rs = rsqrtf(var + 1e-5f);

    const float4* g4 = (const float4*)g;
    const float4* b4 = (const float4*)b;
    float4 gg = g4[t], bb = b4[t];
    float4 o;
    o.x = (v.x - mu) * rs * gg.x + bb.x;
    o.y = (v.y - mu) * rs * gg.y + bb.y;
    o.z = (v.z - mu) * rs * gg.z + bb.z;
    o.w = (v.w - mu) * rs * gg.w + bb.w;
    *(float4*)(out + (size_t)row * DD + t * 4) = o;
}

// ---------------------------------------------------------------------------
// Orchestration
// ---------------------------------------------------------------------------
extern "C" void kernel_launch(void* const* d_in, const int* in_sizes, int n_in,
                              void* d_out, int out_size)
{
    const float* src = (const float*)d_in[0];
    const int*   ei  = (const int*)  d_in[1];
    const float* Wq  = (const float*)d_in[2];
    const float* bq  = (const float*)d_in[3];
    const float* Wk  = (const float*)d_in[4];
    const float* Wv  = (const float*)d_in[5];
    const float* Wo  = (const float*)d_in[6];
    const float* bo  = (const float*)d_in[7];
    const float* W1  = (const float*)d_in[8];
    const float* b1  = (const float*)d_in[9];
    const float* W2  = (const float*)d_in[10];
    const float* b2  = (const float*)d_in[11];
    const float* g1  = (const float*)d_in[12];
    const float* be1 = (const float*)d_in[13];
    const float* g2  = (const float*)d_in[14];
    const float* be2 = (const float*)d_in[15];
    const float* lng = (const float*)d_in[16];
    const float* lnb = (const float*)d_in[17];
    float* outp = (float*)d_out;

    const int n = in_sizes[0] / DD;
    const int E = in_sizes[1] / 2;
    const int* srcI = ei;
    const int* tgtI = ei + E;

    float *q, *k, *v, *agg, *tb, *x, *ff, *p, *m, *s, *sums, *mu, *rs;
    cudaGetSymbolAddress((void**)&q,   g_q);
    cudaGetSymbolAddress((void**)&k,   g_k);
    cudaGetSymbolAddress((void**)&v,   g_v);
    cudaGetSymbolAddress((void**)&agg, g_agg);
    cudaGetSymbolAddress((void**)&tb,  g_t);
    cudaGetSymbolAddress((void**)&x,   g_x);
    cudaGetSymbolAddress((void**)&ff,  g_ff);
    cudaGetSymbolAddress((void**)&p,   g_p);
    cudaGetSymbolAddress((void**)&m,   g_m);
    cudaGetSymbolAddress((void**)&s,   g_s);
    cudaGetSymbolAddress((void**)&sums, g_sums);
    cudaGetSymbolAddress((void**)&mu,  g_mu);
    cudaGetSymbolAddress((void**)&rs,  g_rs);

    const float scaling = 0.125f;   // DH^-0.5, DH=64
    const dim3 gD(DD / 128, (n + 127) / 128);   // GEMM [n, D]
    const dim3 gF(FF / 128, (n + 127) / 128);   // GEMM [n, F]
    const int edgeWarpBlocks = (E + 7) / 8;
    const int edgeEHBlocks   = (E * HH + 255) / 256;
    const int nDblocks       = (n * DD + 255) / 256;

    const float* xin = src;

    for (int l = 0; l < LLAY; l++) {
        const float* Wql = Wq + (size_t)l * DD * DD;
        const float* Wkl = Wk + (size_t)l * DD * DD;
        const float* Wvl = Wv + (size_t)l * DD * DD;
        const float* Wol = Wo + (size_t)l * DD * DD;
        const float* W1l = W1 + (size_t)l * FF * DD;
        const float* W2l = W2 + (size_t)l * DD * FF;

        // q, k, v projections (tensor cores)
        gemm_tf32<false><<<gD, 256>>>(xin, Wql, bq + l * DD, q, n, DD, DD, scaling);
        gemm_tf32<false><<<gD, 256>>>(xin, Wkl, nullptr,     k, n, DD, DD, 1.f);
        gemm_tf32<false><<<gD, 256>>>(xin, Wvl, nullptr,     v, n, DD, DD, 1.f);

        // edge softmax + aggregation
        init_ms<<<(n * HH + 255) / 256, 256>>>(m, s, n * HH);
        fill_k<<<nDblocks, 256>>>(agg, 0.f, n * DD);
        edge_scores<<<edgeWarpBlocks, 256>>>(q, k, srcI, tgtI, p, m, E);
        edge_exp<<<edgeEHBlocks, 256>>>(tgtI, p, m, s, E);
        edge_agg<<<edgeWarpBlocks, 256>>>(v, srcI, tgtI, p, s, agg, E);

        // output projection
        gemm_tf32<false><<<gD, 256>>>(agg, Wol, bo + l * DD, tb, n, DD, DD, 1.f);

        // batchnorm 1 (residual xin + tb)
        fill_k<<<(2 * DD + 255) / 256, 256>>>(sums, 0.f, 2 * DD);
        bn_stats<<<256, DD>>>(xin, tb, sums, n);
        bn_finalize<<<1, DD>>>(sums, mu, rs, 1.f / (float)n);
        bn_apply<<<nDblocks, 256>>>(xin, tb, mu, rs, g1 + l * DD, be1 + l * DD, x, n);

        // feedforward (tensor cores)
        gemm_tf32<true ><<<gF, 256>>>(x, W1l, b1 + l * FF, ff, n, DD, FF, 1.f);
        gemm_tf32<false><<<gD, 256>>>(ff, W2l, b2 + l * DD, tb, n, FF, DD, 1.f);

        // batchnorm 2 (residual x + tb), in-place on x
        fill_k<<<(2 * DD + 255) / 256, 256>>>(sums, 0.f, 2 * DD);
        bn_stats<<<256, DD>>>(x, tb, sums, n);
        bn_finalize<<<1, DD>>>(sums, mu, rs, 1.f / (float)n);
        bn_apply<<<nDblocks, 256>>>(x, tb, mu, rs, g2 + l * DD, be2 + l * DD, x, n);

        xin = x;
    }

    // final layernorm -> output
    layernorm_k<<<n, 128>>>(x, lng, lnb, outp);
}

// round 3
// speedup vs baseline: 3.4866x; 1.5625x over previous
#include <cuda_runtime.h>
#include <math.h>
#include <stdint.h>

// Problem constants (fixed by the reference generator)
#define NN   20000
#define DD   512
#define HH   8
#define DHH  64
#define FF   2048
#define LLAY 2
#define EE   320000
#define QKVW 1536   // packed q|k|v row width

// ---------------------------------------------------------------------------
// Scratch (device globals: alloc-free rule)
// ---------------------------------------------------------------------------
__device__ float g_qkv [NN * QKVW];  // packed q|k|v activations
__device__ float g_agg [NN * DD];
__device__ float g_t   [NN * DD];    // attn-out / ff2-out
__device__ float g_x   [NN * DD];    // running activations
__device__ float g_ff  [NN * FF];
__device__ float g_p   [EE * HH];    // raw scores (CSR order)
__device__ float g_sums[2 * DD];     // batchnorm column sums (sum, sumsq)
__device__ float g_mu  [DD];
__device__ float g_rs  [DD];
__device__ float g_wqkv[LLAY * QKVW * DD];  // packed weights (Wq pre-scaled)
__device__ float g_bqkv[LLAY * QKVW];       // packed bias
// CSR
__device__ int g_cnt [NN + 1];
__device__ int g_off [NN + 1];
__device__ int g_pos [NN];
__device__ int g_esrc[EE];

// ---------------------------------------------------------------------------
// Utility kernels
// ---------------------------------------------------------------------------
__global__ void fill_f(float* __restrict__ p, float v, int n) {
    int i = blockIdx.x * blockDim.x + threadIdx.x;
    if (i < n) p[i] = v;
}
__global__ void fill_i(int* __restrict__ p, int v, int n) {
    int i = blockIdx.x * blockDim.x + threadIdx.x;
    if (i < n) p[i] = v;
}

// ---------------------------------------------------------------------------
// Weight packing:  wout[l][r][c], r<512: Wq*0.125 | r<1024: Wk | else Wv
// ---------------------------------------------------------------------------
__global__ void pack_qkv_w(const float* __restrict__ Wq, const float* __restrict__ Wk,
                           const float* __restrict__ Wv, float* __restrict__ wout)
{
    int idx = blockIdx.x * blockDim.x + threadIdx.x;
    const int total = LLAY * QKVW * DD;
    if (idx >= total) return;
    int l = idx / (QKVW * DD);
    int rem = idx % (QKVW * DD);
    int r = rem / DD, c = rem % DD;
    float val;
    if (r < 512)       val = Wq[(size_t)l * DD * DD + (size_t)r * DD + c] * 0.125f;
    else if (r < 1024) val = Wk[(size_t)l * DD * DD + (size_t)(r - 512) * DD + c];
    else               val = Wv[(size_t)l * DD * DD + (size_t)(r - 1024) * DD + c];
    wout[idx] = val;
}
__global__ void pack_qkv_b(const float* __restrict__ bq, float* __restrict__ bout)
{
    int idx = blockIdx.x * blockDim.x + threadIdx.x;
    if (idx >= LLAY * QKVW) return;
    int l = idx / QKVW, r = idx % QKVW;
    bout[idx] = (r < 512) ? bq[l * DD + r] * 0.125f : 0.f;
}

// ---------------------------------------------------------------------------
// CSR build
// ---------------------------------------------------------------------------
__global__ void csr_hist(const int* __restrict__ tgtI, int* __restrict__ cnt, int E)
{
    int e = blockIdx.x * blockDim.x + threadIdx.x;
    if (e < E) atomicAdd(&cnt[tgtI[e]], 1);
}

// single block, 1024 threads; n <= 32768
__global__ void __launch_bounds__(1024)
csr_scan(const int* __restrict__ cnt, int* __restrict__ off, int* __restrict__ pos, int n)
{
    __shared__ int part[1024];
    const int t = threadIdx.x;
    const int CH = (n + 1023) / 1024;   // 20 for n=20000
    int vals[32];
    int base = t * CH;
    int local = 0;
    for (int i = 0; i < CH; i++) {
        int e = base + i;
        int v = (e < n) ? cnt[e] : 0;
        vals[i] = v;
        local += v;
    }
    part[t] = local;
    __syncthreads();
    // Hillis-Steele inclusive scan
    for (int d = 1; d < 1024; d <<= 1) {
        int v = (t >= d) ? part[t - d] : 0;
        __syncthreads();
        part[t] += v;
        __syncthreads();
    }
    int run = (t > 0) ? part[t - 1] : 0;
    for (int i = 0; i < CH; i++) {
        int e = base + i;
        if (e < n) { off[e] = run; pos[e] = run; run += vals[i]; }
    }
    if (t == 1023) off[n] = part[1023];
}

__global__ void csr_scatter(const int* __restrict__ srcI, const int* __restrict__ tgtI,
                            int* __restrict__ pos, int* __restrict__ esrc, int E)
{
    int e = blockIdx.x * blockDim.x + threadIdx.x;
    if (e >= E) return;
    int slot = atomicAdd(&pos[tgtI[e]], 1);
    esrc[slot] = srcI[e];
}

// ---------------------------------------------------------------------------
// Attention over CSR: one warp per target node, no atomics.
// qkv row layout: [q(512) | k(512) | v(512)], lane owns 16 contiguous dims,
// lane's head = lane>>2 (16 dims always within one 64-dim head).
// ---------------------------------------------------------------------------
__global__ void __launch_bounds__(256)
attn_csr(const float* __restrict__ qkv, const int* __restrict__ off,
         const int* __restrict__ esrc, float* __restrict__ p,
         float* __restrict__ agg, int n)
{
    int node = (blockIdx.x * blockDim.x + threadIdx.x) >> 5;
    int lane = threadIdx.x & 31;
    if (node >= n) return;
    const int start = off[node];
    const int end   = off[node + 1];
    const int h     = lane >> 2;

    const float4* qr = (const float4*)(qkv + (size_t)node * QKVW) + lane * 4;
    float4 q0 = qr[0], q1 = qr[1], q2 = qr[2], q3 = qr[3];

    // pass 1: scores + per-head max
    float hmax = -INFINITY;
    for (int s = start; s < end; s++) {
        int sn = esrc[s];
        const float4* kr = (const float4*)(qkv + (size_t)sn * QKVW + 512) + lane * 4;
        float4 k0 = kr[0], k1 = kr[1], k2 = kr[2], k3 = kr[3];
        float d = q0.x*k0.x + q0.y*k0.y + q0.z*k0.z + q0.w*k0.w;
        d += q1.x*k1.x + q1.y*k1.y + q1.z*k1.z + q1.w*k1.w;
        d += q2.x*k2.x + q2.y*k2.y + q2.z*k2.z + q2.w*k2.w;
        d += q3.x*k3.x + q3.y*k3.y + q3.z*k3.z + q3.w*k3.w;
        d += __shfl_xor_sync(0xffffffffu, d, 1);
        d += __shfl_xor_sync(0xffffffffu, d, 2);
        if ((lane & 3) == 0) p[(size_t)s * HH + h] = d;
        hmax = fmaxf(hmax, d);
    }

    // pass 2: exp, sum, weighted v aggregation
    float acc[16];
#pragma unroll
    for (int i = 0; i < 16; i++) acc[i] = 0.f;
    float hsum = 0.f;

    for (int s = start; s < end; s++) {
        int sn = esrc[s];
        float d = p[(size_t)s * HH + h];
        float w = expf(d - hmax);
        hsum += w;
        const float4* vr = (const float4*)(qkv + (size_t)sn * QKVW + 1024) + lane * 4;
        float4 v0 = vr[0], v1 = vr[1], v2 = vr[2], v3 = vr[3];
        acc[0]  += w * v0.x; acc[1]  += w * v0.y; acc[2]  += w * v0.z; acc[3]  += w * v0.w;
        acc[4]  += w * v1.x; acc[5]  += w * v1.y; acc[6]  += w * v1.z; acc[7]  += w * v1.w;
        acc[8]  += w * v2.x; acc[9]  += w * v2.y; acc[10] += w * v2.z; acc[11] += w * v2.w;
        acc[12] += w * v3.x; acc[13] += w * v3.y; acc[14] += w * v3.z; acc[15] += w * v3.w;
    }

    float inv = 1.f / (hsum + 1e-16f);
    float4* ag = (float4*)(agg + (size_t)node * DD) + lane * 4;
#pragma unroll
    for (int i = 0; i < 4; i++)
        ag[i] = make_float4(acc[i*4+0]*inv, acc[i*4+1]*inv, acc[i*4+2]*inv, acc[i*4+3]*inv);
}

// ---------------------------------------------------------------------------
// TF32 tensor-core GEMM: C[M,Nout] = act((A[M,K] @ W[Nout,K]^T + bias)*scale)
// Block tile 128x128, BK=32, 256 threads (8 warps, 2x4), warp tile 64x32.
// ---------------------------------------------------------------------------
__device__ __forceinline__ uint32_t f2tf(float x) {
    uint32_t r;
    asm("cvt.rna.tf32.f32 %0, %1;" : "=r"(r) : "f"(x));
    return r;
}

template <bool RELU>
__global__ void __launch_bounds__(256, 1)
gemm_tf32(const float* __restrict__ A, const float* __restrict__ W,
          const float* __restrict__ bias, float* __restrict__ C,
          int M, int K, int Nout, float scale)
{
    __shared__ float As[128][36];   // [m][k] padded: frag loads conflict-free
    __shared__ float Bs[128][36];   // [n][k]

    const int tid  = threadIdx.x;
    const int lane = tid & 31;
    const int warp = tid >> 5;
    const int wm   = warp >> 2;     // 0..1
    const int wn   = warp & 3;      // 0..3
    const int g    = lane >> 2;     // 0..7
    const int c    = lane & 3;      // 0..3
    const int rowBase = blockIdx.y * 128;
    const int colBase = blockIdx.x * 128;

    float acc[4][4][4];
#pragma unroll
    for (int mt = 0; mt < 4; mt++)
#pragma unroll
        for (int nt = 0; nt < 4; nt++)
#pragma unroll
            for (int i = 0; i < 4; i++) acc[mt][nt][i] = 0.f;

    float4 aR[4], bR[4];

    auto loadTiles = [&](int k0) {
#pragma unroll
        for (int i = 0; i < 4; i++) {
            int li = tid + i * 256;       // 0..1023 float4 slots
            int r  = li >> 3;             // 0..127
            int q  = li & 7;              // 0..7 (quad of 4 k's)
            int ar = rowBase + r;
            aR[i] = (ar < M) ? *(const float4*)(A + (size_t)ar * K + k0 + q * 4)
                             : make_float4(0.f, 0.f, 0.f, 0.f);
            bR[i] = *(const float4*)(W + (size_t)(colBase + r) * K + k0 + q * 4);
        }
    };

    auto storeTiles = [&]() {
#pragma unroll
        for (int i = 0; i < 4; i++) {
            int li = tid + i * 256;
            int r  = li >> 3;
            int q  = li & 7;
            float4 av, bv;
            av.x = __uint_as_float(f2tf(aR[i].x));
            av.y = __uint_as_float(f2tf(aR[i].y));
            av.z = __uint_as_float(f2tf(aR[i].z));
            av.w = __uint_as_float(f2tf(aR[i].w));
            bv.x = __uint_as_float(f2tf(bR[i].x));
            bv.y = __uint_as_float(f2tf(bR[i].y));
            bv.z = __uint_as_float(f2tf(bR[i].z));
            bv.w = __uint_as_float(f2tf(bR[i].w));
            *(float4*)&As[r][q * 4] = av;
            *(float4*)&Bs[r][q * 4] = bv;
        }
    };

    loadTiles(0);
    const int nIter = K >> 5;

    for (int kt = 0; kt < nIter; kt++) {
        __syncthreads();
        storeTiles();
        __syncthreads();
        if (kt + 1 < nIter) loadTiles((kt + 1) << 5);

#pragma unroll
        for (int ks = 0; ks < 4; ks++) {
            uint32_t af[4][4];
            uint32_t bf[4][2];
#pragma unroll
            for (int mt = 0; mt < 4; mt++) {
                int r0 = wm * 64 + mt * 16 + g;
                af[mt][0] = __float_as_uint(As[r0    ][ks * 8 + c    ]);
                af[mt][1] = __float_as_uint(As[r0 + 8][ks * 8 + c    ]);
                af[mt][2] = __float_as_uint(As[r0    ][ks * 8 + c + 4]);
                af[mt][3] = __float_as_uint(As[r0 + 8][ks * 8 + c + 4]);
            }
#pragma unroll
            for (int nt = 0; nt < 4; nt++) {
                int n0 = wn * 32 + nt * 8 + g;
                bf[nt][0] = __float_as_uint(Bs[n0][ks * 8 + c    ]);
                bf[nt][1] = __float_as_uint(Bs[n0][ks * 8 + c + 4]);
            }
#pragma unroll
            for (int mt = 0; mt < 4; mt++)
#pragma unroll
                for (int nt = 0; nt < 4; nt++)
                    asm volatile(
                        "mma.sync.aligned.m16n8k8.row.col.f32.tf32.tf32.f32 "
                        "{%0,%1,%2,%3}, {%4,%5,%6,%7}, {%8,%9}, {%0,%1,%2,%3};"
                        : "+f"(acc[mt][nt][0]), "+f"(acc[mt][nt][1]),
                          "+f"(acc[mt][nt][2]), "+f"(acc[mt][nt][3])
                        : "r"(af[mt][0]), "r"(af[mt][1]),
                          "r"(af[mt][2]), "r"(af[mt][3]),
                          "r"(bf[nt][0]), "r"(bf[nt][1]));
        }
    }

    // Epilogue: bias, scale, relu, guarded float2 stores
#pragma unroll
    for (int mt = 0; mt < 4; mt++) {
        int r0 = rowBase + wm * 64 + mt * 16 + g;
        int r1 = r0 + 8;
#pragma unroll
        for (int nt = 0; nt < 4; nt++) {
            int col = colBase + wn * 32 + nt * 8 + c * 2;
            float bx = 0.f, by = 0.f;
            if (bias) { float2 bb = *(const float2*)(bias + col); bx = bb.x; by = bb.y; }
            float v0 = (acc[mt][nt][0] + bx) * scale;
            float v1 = (acc[mt][nt][1] + by) * scale;
            float v2 = (acc[mt][nt][2] + bx) * scale;
            float v3 = (acc[mt][nt][3] + by) * scale;
            if (RELU) {
                v0 = fmaxf(v0, 0.f); v1 = fmaxf(v1, 0.f);
                v2 = fmaxf(v2, 0.f); v3 = fmaxf(v3, 0.f);
            }
            if (r0 < M) *(float2*)(C + (size_t)r0 * Nout + col) = make_float2(v0, v1);
            if (r1 < M) *(float2*)(C + (size_t)r1 * Nout + col) = make_float2(v2, v3);
        }
    }
}

// ---------------------------------------------------------------------------
// BatchNorm over node dimension on z = a + b (residual fused)
// ---------------------------------------------------------------------------
__global__ void bn_stats(const float* __restrict__ a, const float* __restrict__ b,
                         float* __restrict__ sums, int n)
{
    int j = threadIdx.x;   // 512 threads = one per feature
    float sum = 0.f, sq = 0.f;
    for (int i = blockIdx.x; i < n; i += gridDim.x) {
        float z = a[(size_t)i * DD + j] + b[(size_t)i * DD + j];
        sum += z; sq += z * z;
    }
    atomicAdd(&sums[j], sum);
    atomicAdd(&sums[DD + j], sq);
}

__global__ void bn_finalize(const float* __restrict__ sums,
                            float* __restrict__ mu, float* __restrict__ rs, float invn)
{
    int j = threadIdx.x;
    float m = sums[j] * invn;
    float var = sums[DD + j] * invn - m * m;
    mu[j] = m;
    rs[j] = rsqrtf(var + 1e-5f);
}

__global__ void bn_apply(const float* __restrict__ a, const float* __restrict__ b,
                         const float* __restrict__ mu, const float* __restrict__ rs,
                         const float* __restrict__ g, const float* __restrict__ beta,
                         float* __restrict__ out, int n)
{
    int idx = blockIdx.x * blockDim.x + threadIdx.x;
    if (idx >= n * DD) return;
    int j = idx & (DD - 1);
    float z = a[idx] + b[idx];
    out[idx] = (z - mu[j]) * rs[j] * g[j] + beta[j];
}

// ---------------------------------------------------------------------------
// Final per-row LayerNorm  (128 threads/row, 4 floats each)
// ---------------------------------------------------------------------------
__global__ void layernorm_k(const float* __restrict__ x, const float* __restrict__ g,
                            const float* __restrict__ b, float* __restrict__ out)
{
    int row = blockIdx.x;
    int t = threadIdx.x;
    const float4* xr = (const float4*)(x + (size_t)row * DD);
    float4 v = xr[t];
    float sum = v.x + v.y + v.z + v.w;
    float sq  = v.x * v.x + v.y * v.y + v.z * v.z + v.w * v.w;

#pragma unroll
    for (int o = 16; o > 0; o >>= 1) {
        sum += __shfl_xor_sync(0xffffffffu, sum, o);
        sq  += __shfl_xor_sync(0xffffffffu, sq, o);
    }
    __shared__ float sa[4], sb[4];
    int w = t >> 5, l = t & 31;
    if (l == 0) { sa[w] = sum; sb[w] = sq; }
    __syncthreads();
    sum = sa[0] + sa[1] + sa[2] + sa[3];
    sq  = sb[0] + sb[1] + sb[2] + sb[3];

    float mu = sum * (1.f / DD);
    float var = sq * (1.f / DD) - mu * mu;
    float rs = rsqrtf(var + 1e-5f);

    const float4* g4 = (const float4*)g;
    const float4* b4 = (const float4*)b;
    float4 gg = g4[t], bb = b4[t];
    float4 o;
    o.x = (v.x - mu) * rs * gg.x + bb.x;
    o.y = (v.y - mu) * rs * gg.y + bb.y;
    o.z = (v.z - mu) * rs * gg.z + bb.z;
    o.w = (v.w - mu) * rs * gg.w + bb.w;
    *(float4*)(out + (size_t)row * DD + t * 4) = o;
}

// ---------------------------------------------------------------------------
// Orchestration
// ---------------------------------------------------------------------------
extern "C" void kernel_launch(void* const* d_in, const int* in_sizes, int n_in,
                              void* d_out, int out_size)
{
    const float* src = (const float*)d_in[0];
    const int*   ei  = (const int*)  d_in[1];
    const float* Wq  = (const float*)d_in[2];
    const float* bq  = (const float*)d_in[3];
    const float* Wk  = (const float*)d_in[4];
    const float* Wv  = (const float*)d_in[5];
    const float* Wo  = (const float*)d_in[6];
    const float* bo  = (const float*)d_in[7];
    const float* W1  = (const float*)d_in[8];
    const float* b1  = (const float*)d_in[9];
    const float* W2  = (const float*)d_in[10];
    const float* b2  = (const float*)d_in[11];
    const float* g1  = (const float*)d_in[12];
    const float* be1 = (const float*)d_in[13];
    const float* g2  = (const float*)d_in[14];
    const float* be2 = (const float*)d_in[15];
    const float* lng = (const float*)d_in[16];
    const float* lnb = (const float*)d_in[17];
    float* outp = (float*)d_out;

    const int n = in_sizes[0] / DD;
    const int E = in_sizes[1] / 2;
    const int* srcI = ei;
    const int* tgtI = ei + E;

    float *qkv, *agg, *tb, *x, *ff, *p, *sums, *mu, *rs, *wqkv, *bqkv;
    int *cnt, *off, *pos, *esrc;
    cudaGetSymbolAddress((void**)&qkv,  g_qkv);
    cudaGetSymbolAddress((void**)&agg,  g_agg);
    cudaGetSymbolAddress((void**)&tb,   g_t);
    cudaGetSymbolAddress((void**)&x,    g_x);
    cudaGetSymbolAddress((void**)&ff,   g_ff);
    cudaGetSymbolAddress((void**)&p,    g_p);
    cudaGetSymbolAddress((void**)&sums, g_sums);
    cudaGetSymbolAddress((void**)&mu,   g_mu);
    cudaGetSymbolAddress((void**)&rs,   g_rs);
    cudaGetSymbolAddress((void**)&wqkv, g_wqkv);
    cudaGetSymbolAddress((void**)&bqkv, g_bqkv);
    cudaGetSymbolAddress((void**)&cnt,  g_cnt);
    cudaGetSymbolAddress((void**)&off,  g_off);
    cudaGetSymbolAddress((void**)&pos,  g_pos);
    cudaGetSymbolAddress((void**)&esrc, g_esrc);

    const dim3 gQKV(QKVW / 128, (n + 127) / 128);
    const dim3 gD(DD / 128, (n + 127) / 128);
    const dim3 gF(FF / 128, (n + 127) / 128);
    const int nDblocks = (n * DD + 255) / 256;

    // ---- weight packing (per launch, deterministic) ----
    pack_qkv_w<<<(LLAY * QKVW * DD + 255) / 256, 256>>>(Wq, Wk, Wv, wqkv);
    pack_qkv_b<<<(LLAY * QKVW + 255) / 256, 256>>>(bq, bqkv);

    // ---- CSR build (edge structure shared by both layers) ----
    fill_i<<<(n + 1 + 255) / 256, 256>>>(cnt, 0, n + 1);
    csr_hist<<<(E + 255) / 256, 256>>>(tgtI, cnt, E);
    csr_scan<<<1, 1024>>>(cnt, off, pos, n);
    csr_scatter<<<(E + 255) / 256, 256>>>(srcI, tgtI, pos, esrc, E);

    const float* xin = src;

    for (int l = 0; l < LLAY; l++) {
        const float* Wol = Wo + (size_t)l * DD * DD;
        const float* W1l = W1 + (size_t)l * FF * DD;
        const float* W2l = W2 + (size_t)l * DD * FF;

        // fused q|k|v projection (q already pre-scaled in packed weights)
        gemm_tf32<false><<<gQKV, 256>>>(xin, wqkv + (size_t)l * QKVW * DD,
                                        bqkv + l * QKVW, qkv, n, DD, QKVW, 1.f);

        // attention over CSR (no atomics)
        attn_csr<<<(n * 32 + 255) / 256, 256>>>(qkv, off, esrc, p, agg, n);

        // output projection
        gemm_tf32<false><<<gD, 256>>>(agg, Wol, bo + l * DD, tb, n, DD, DD, 1.f);

        // batchnorm 1 (residual xin + tb)
        fill_f<<<(2 * DD + 255) / 256, 256>>>(sums, 0.f, 2 * DD);
        bn_stats<<<256, DD>>>(xin, tb, sums, n);
        bn_finalize<<<1, DD>>>(sums, mu, rs, 1.f / (float)n);
        bn_apply<<<nDblocks, 256>>>(xin, tb, mu, rs, g1 + l * DD, be1 + l * DD, x, n);

        // feedforward
        gemm_tf32<true ><<<gF, 256>>>(x, W1l, b1 + l * FF, ff, n, DD, FF, 1.f);
        gemm_tf32<false><<<gD, 256>>>(ff, W2l, b2 + l * DD, tb, n, FF, DD, 1.f);

        // batchnorm 2 (residual x + tb), in-place on x
        fill_f<<<(2 * DD + 255) / 256, 256>>>(sums, 0.f, 2 * DD);
        bn_stats<<<256, DD>>>(x, tb, sums, n);
        bn_finalize<<<1, DD>>>(sums, mu, rs, 1.f / (float)n);
        bn_apply<<<nDblocks, 256>>>(x, tb, mu, rs, g2 + l * DD, be2 + l * DD, x, n);

        xin = x;
    }

    // final layernorm -> output
    layernorm_k<<<n, 128>>>(x, lng, lnb, outp);
}